// round 3
// baseline (speedup 1.0000x reference)
#include <cuda_runtime.h>

// Problem constants
#define HB 40
#define WB 40
#define HWB 1600          // 40*40
#define CIN 256
#define CMID 64
#define CENC 100
#define NBATCH 2

// Scratch (device globals; no allocation allowed)
__device__ float g_comp[NBATCH * CMID * HWB];   // (b,64,40,40)
__device__ float g_enc[NBATCH * CENC * HWB];    // (b,100,40,40)

// ---------------------------------------------------------------------------
// K1: 1x1 conv (channel compressor): comp[b,co,p] = sum_ci w[co,ci]*x[b,ci,p]
// Tiled GEMM: 16 pixels x 64 co per block, ci chunked by 128.
// ---------------------------------------------------------------------------
__global__ __launch_bounds__(256) void k1_compress(
    const float* __restrict__ x, const float* __restrict__ wcomp)
{
    __shared__ float xs[128 * 16];      // [ci_local][pl]
    __shared__ float ws[128 * 65];      // [ci_local][co], padded stride 65

    const int b  = blockIdx.y;
    const int p0 = blockIdx.x * 16;
    const int tid = threadIdx.x;
    const int pl = tid & 15;            // pixel lane 0..15
    const int cg = tid >> 4;            // co group 0..15; co = cg + 16*r

    float acc0 = 0.f, acc1 = 0.f, acc2 = 0.f, acc3 = 0.f;

    for (int ci0 = 0; ci0 < CIN; ci0 += 128) {
        // load x tile (coalesced in 64B segments)
        #pragma unroll
        for (int i = tid; i < 128 * 16; i += 256) {
            int ci = i >> 4, pp = i & 15;
            xs[i] = x[(size_t)((b * CIN + ci0 + ci) * HWB) + p0 + pp];
        }
        // load w chunk, transpose into [ci][co] with pad-65 (conflict-free STS)
        #pragma unroll
        for (int i = tid; i < 128 * 64; i += 256) {
            int co = i >> 7, ci = i & 127;
            ws[ci * 65 + co] = wcomp[co * CIN + ci0 + ci];
        }
        __syncthreads();

        #pragma unroll 8
        for (int ci = 0; ci < 128; ++ci) {
            float xv = xs[ci * 16 + pl];
            const float* wr = &ws[ci * 65 + cg];
            acc0 = fmaf(xv, wr[0],  acc0);
            acc1 = fmaf(xv, wr[16], acc1);
            acc2 = fmaf(xv, wr[32], acc2);
            acc3 = fmaf(xv, wr[48], acc3);
        }
        __syncthreads();
    }

    const int p = p0 + pl;
    g_comp[(b * CMID + cg     ) * HWB + p] = acc0;
    g_comp[(b * CMID + cg + 16) * HWB + p] = acc1;
    g_comp[(b * CMID + cg + 32) * HWB + p] = acc2;
    g_comp[(b * CMID + cg + 48) * HWB + p] = acc3;
}

// ---------------------------------------------------------------------------
// K2: 3x3 conv 64->100 (content encoder), pad 1.
// Block: 10 output channels x 8x8 pixel tile. smem: x halo tile + weight slice.
// Thread: 1 pixel x 5 channels (cg in {0,1}).
// ---------------------------------------------------------------------------
#define K2_CO 10
__global__ __launch_bounds__(128) void k2_encoder(const float* __restrict__ wenc)
{
    __shared__ float xs[64 * 100];        // [ci][hh*10+ww], 10x10 halo tile
    __shared__ float ws[K2_CO * 576];     // [co_local][ci*9+tap]

    const int tile = blockIdx.x;          // 0..24
    const int co0  = blockIdx.y * K2_CO;  // 0,10,...,90
    const int b    = blockIdx.z;
    const int h0 = (tile / 5) * 8, w0 = (tile % 5) * 8;
    const int tid = threadIdx.x;

    // load input halo tile (zero-padded)
    for (int i = tid; i < 64 * 100; i += 128) {
        int ci = i / 100, r = i % 100;
        int hh = r / 10, ww = r % 10;
        int gh = h0 - 1 + hh, gw = w0 - 1 + ww;
        float v = 0.f;
        if ((unsigned)gh < (unsigned)HB && (unsigned)gw < (unsigned)WB)
            v = g_comp[(b * CMID + ci) * HWB + gh * WB + gw];
        xs[i] = v;
    }
    // load weight slice (coalesced, linear)
    for (int i = tid; i < K2_CO * 576; i += 128)
        ws[i] = wenc[co0 * 576 + i];
    __syncthreads();

    const int px = tid & 63;              // 0..63
    const int cg = tid >> 6;              // 0..1
    const int ph = px >> 3, pw = px & 7;

    float acc[5] = {0.f, 0.f, 0.f, 0.f, 0.f};

    #pragma unroll 2
    for (int ci = 0; ci < 64; ++ci) {
        const float* xrow = &xs[ci * 100 + ph * 10 + pw];
        const float* wrow = &ws[(cg * 5) * 576 + ci * 9];
        #pragma unroll
        for (int tap = 0; tap < 9; ++tap) {
            float xv = xrow[(tap / 3) * 10 + (tap % 3)];
            #pragma unroll
            for (int r = 0; r < 5; ++r)
                acc[r] = fmaf(xv, wrow[r * 576 + tap], acc[r]);
        }
    }

    const int sp = (h0 + ph) * WB + (w0 + pw);
    #pragma unroll
    for (int r = 0; r < 5; ++r)
        g_enc[(b * CENC + co0 + cg * 5 + r) * HWB + sp] = acc[r];
}

// ---------------------------------------------------------------------------
// K3: fused softmax + reassembly.
// For output (p, d): L = 4p+d. Pixel-shuffle/reshape quirk gives weight source
//   t2 = 2*pw + d/2;  si = t2/40;  wc = t2%40;  sj = d&1
//   logit_k = enc[b, k*4 + si*2 + sj, ph, wc]
// out[b,c,p,d] = sum_k x_pad[b,c,ph+ki-2,pw+kj-2] * softmax_k(logit)[k]
// Block: 32 pixels x 128 channels. Weights softmaxed into smem, then register-
// cached (100 regs) per thread for the channel loop.
// ---------------------------------------------------------------------------
__global__ __launch_bounds__(256) void k3_reassemble(
    const float* __restrict__ x, float* __restrict__ out)
{
    __shared__ float wsm[32 * 101];   // [pl][d*25+k], pad-101 (conflict-free)

    const int p0 = blockIdx.x * 32;
    const int c0 = blockIdx.y * 128;
    const int b  = blockIdx.z;
    const int tid = threadIdx.x;

    // ---- Phase A: softmax weights for 32 pixels x 4 subpixels (128 threads)
    if (tid < 128) {
        const int pl = tid & 31, d = tid >> 5;
        const int p  = p0 + pl;
        const int ph = p / WB, pw = p % WB;
        const int t2 = 2 * pw + (d >> 1);
        const int si = (t2 >= WB) ? 1 : 0;
        const int wc = t2 - WB * si;
        const int sj = d & 1;
        const float* ebase = g_enc + (size_t)(b * CENC + si * 2 + sj) * HWB + ph * WB + wc;

        float v[25];
        #pragma unroll
        for (int k = 0; k < 25; ++k) v[k] = ebase[(size_t)k * 4 * HWB];
        float m = v[0];
        #pragma unroll
        for (int k = 1; k < 25; ++k) m = fmaxf(m, v[k]);
        float s = 0.f;
        #pragma unroll
        for (int k = 0; k < 25; ++k) { v[k] = __expf(v[k] - m); s += v[k]; }
        float inv = 1.f / s;
        #pragma unroll
        for (int k = 0; k < 25; ++k) wsm[pl * 101 + d * 25 + k] = v[k] * inv;
    }
    __syncthreads();

    // ---- Phase B: reassembly
    const int pl = tid & 31, cq = tid >> 5;       // cq 0..7
    const int p  = p0 + pl;
    const int ph = p / WB, pw = p % WB;

    unsigned mask = 0;
    #pragma unroll
    for (int k = 0; k < 25; ++k) {
        int di = k / 5 - 2, dj = k % 5 - 2;
        if ((unsigned)(ph + di) < (unsigned)HB && (unsigned)(pw + dj) < (unsigned)WB)
            mask |= 1u << k;
    }

    float wr[100];
    #pragma unroll
    for (int j = 0; j < 100; ++j) wr[j] = wsm[pl * 101 + j];

    for (int it = 0; it < 16; ++it) {
        const int c = c0 + cq + (it << 3);
        const float* xb = x + (size_t)((b * CIN + c) * HWB) + p;
        float a0 = 0.f, a1 = 0.f, a2 = 0.f, a3 = 0.f;
        #pragma unroll
        for (int k = 0; k < 25; ++k) {
            float xv = 0.f;
            if (mask & (1u << k))
                xv = __ldg(xb + (k / 5 - 2) * WB + (k % 5 - 2));
            a0 = fmaf(xv, wr[k],      a0);
            a1 = fmaf(xv, wr[25 + k], a1);
            a2 = fmaf(xv, wr[50 + k], a2);
            a3 = fmaf(xv, wr[75 + k], a3);
        }
        float4 o = make_float4(a0, a1, a2, a3);
        *reinterpret_cast<float4*>(out + (size_t)(b * CIN + c) * 6400 + 4 * p) = o;
    }
}

// ---------------------------------------------------------------------------
extern "C" void kernel_launch(void* const* d_in, const int* in_sizes, int n_in,
                              void* d_out, int out_size)
{
    const float* x      = (const float*)d_in[0];   // (2,256,40,40)
    const float* w_comp = (const float*)d_in[1];   // (64,256,1,1)
    const float* w_enc  = (const float*)d_in[2];   // (100,64,3,3)
    float* out = (float*)d_out;                    // (2,256,80,80)

    k1_compress  <<<dim3(HWB / 16, NBATCH),      256>>>(x, w_comp);
    k2_encoder   <<<dim3(25, CENC / K2_CO, NBATCH), 128>>>(w_enc);
    k3_reassemble<<<dim3(HWB / 32, 2, NBATCH),   256>>>(x, out);
}

// round 6
// speedup vs baseline: 1.4716x; 1.4716x over previous
#include <cuda_runtime.h>

#define HB 40
#define WB 40
#define HWB 1600          // 40*40
#define CIN 256
#define CMID 64
#define CENC 100
#define NBATCH 2

// Scratch (device globals; no allocation allowed)
__device__ float g_comp[NBATCH * CMID * HWB];   // (b,64,40,40)
__device__ float g_enc[NBATCH * CENC * HWB];    // (b,100,40,40)

typedef unsigned long long u64;

// ---- packed fp32x2 helpers (sm_103a FFMA2 via PTX) ----
__device__ __forceinline__ u64 pack2(float x, float y) {
    u64 r; asm("mov.b64 %0, {%1, %2};" : "=l"(r) : "f"(x), "f"(y)); return r;
}
__device__ __forceinline__ void ffma2(u64 &d, u64 a, u64 b) {
    asm("fma.rn.f32x2 %0, %1, %2, %0;" : "+l"(d) : "l"(a), "l"(b));
}
__device__ __forceinline__ float2 unpack2(u64 v) {
    float2 f; asm("mov.b64 {%0, %1}, %2;" : "=f"(f.x), "=f"(f.y) : "l"(v)); return f;
}

// ---------------------------------------------------------------------------
// K1: 1x1 conv. thread = pixel, 8 output channels via 4 FFMA2.
// grid (10 px-chunks x 160 threads = 1600 px, 8 co-groups, 2 batch).
// ---------------------------------------------------------------------------
__global__ __launch_bounds__(160) void k1_compress(
    const float* __restrict__ x, const float* __restrict__ wcomp)
{
    __shared__ __align__(16) float ws[CIN * 8];   // [ci][co(8)]

    const int tid = threadIdx.x;
    const int p   = blockIdx.x * 160 + tid;       // 10*160 = 1600 = HWB exactly
    const int co0 = blockIdx.y * 8;
    const int b   = blockIdx.z;

    for (int i = tid; i < CIN * 8; i += 160) {
        int co = i >> 8, ci = i & 255;                 // coalesced read in ci
        ws[ci * 8 + co] = wcomp[(co0 + co) * CIN + ci];
    }
    __syncthreads();

    const float* xb = x + (size_t)(b * CIN) * HWB + p;
    u64 acc0 = 0, acc1 = 0, acc2 = 0, acc3 = 0;       // (0.f,0.f) bit pattern

    #pragma unroll 8
    for (int ci = 0; ci < CIN; ++ci) {
        float xv = xb[(size_t)ci * HWB];
        u64 xx = pack2(xv, xv);
        const u64* wr = (const u64*)&ws[ci * 8];       // broadcast LDS.64
        ffma2(acc0, xx, wr[0]);
        ffma2(acc1, xx, wr[1]);
        ffma2(acc2, xx, wr[2]);
        ffma2(acc3, xx, wr[3]);
    }

    float* ob = g_comp + (size_t)(b * CMID + co0) * HWB + p;
    float2 v;
    v = unpack2(acc0); ob[0 * HWB] = v.x; ob[1 * HWB] = v.y;
    v = unpack2(acc1); ob[2 * HWB] = v.x; ob[3 * HWB] = v.y;
    v = unpack2(acc2); ob[4 * HWB] = v.x; ob[5 * HWB] = v.y;
    v = unpack2(acc3); ob[6 * HWB] = v.x; ob[7 * HWB] = v.y;
}

// ---------------------------------------------------------------------------
// K2: 3x3 conv 64->100, pad 1. Block: 8x8 px tile x 10 co.
// 128 threads = 64 px x 2 ci-halves; thread computes all 10 co over 32 ci
// (5 FFMA2 per tap), then smem reduce across halves.
// Weights in smem as [ci*9+tap][co] so the 10 co read as 5 LDS.64 broadcasts.
// ---------------------------------------------------------------------------
__global__ __launch_bounds__(128) void k2_encoder(const float* __restrict__ wenc)
{
    __shared__ __align__(16) float xs[64 * 100];      // [ci][10x10 halo]
    __shared__ __align__(16) float ws[576 * 10];      // [ci*9+tap][co]

    const int tile = blockIdx.x;                      // 0..24
    const int co0  = blockIdx.y * 10;
    const int b    = blockIdx.z;
    const int h0 = (tile / 5) * 8, w0 = (tile % 5) * 8;
    const int tid = threadIdx.x;

    for (int i = tid; i < 64 * 100; i += 128) {
        int ci = i / 100, r = i - ci * 100;
        int hh = r / 10, ww = r - hh * 10;
        int gh = h0 - 1 + hh, gw = w0 - 1 + ww;
        float v = 0.f;
        if ((unsigned)gh < (unsigned)HB && (unsigned)gw < (unsigned)WB)
            v = g_comp[(b * CMID + ci) * HWB + gh * WB + gw];
        xs[i] = v;
    }
    for (int i = tid; i < 5760; i += 128) {
        int c = i / 576, idx = i - c * 576;           // coalesced read in idx
        ws[idx * 10 + c] = wenc[(co0 + c) * 576 + idx];
    }
    __syncthreads();

    const int px = tid & 63;
    const int hhalf = tid >> 6;                       // ci half
    const int ph = px >> 3, pw = px & 7;

    u64 acc[5] = {0, 0, 0, 0, 0};
    const int ci0 = hhalf * 32;

    #pragma unroll 2
    for (int ci = ci0; ci < ci0 + 32; ++ci) {
        const float* xrow = &xs[ci * 100 + ph * 10 + pw];
        const float* wb0  = &ws[ci * 90];
        #pragma unroll
        for (int tr = 0; tr < 3; ++tr)
        #pragma unroll
        for (int tc = 0; tc < 3; ++tc) {
            float xv = xrow[tr * 10 + tc];
            u64 xx = pack2(xv, xv);
            const u64* wp = (const u64*)(wb0 + (tr * 3 + tc) * 10);
            ffma2(acc[0], xx, wp[0]);
            ffma2(acc[1], xx, wp[1]);
            ffma2(acc[2], xx, wp[2]);
            ffma2(acc[3], xx, wp[3]);
            ffma2(acc[4], xx, wp[4]);
        }
    }

    __syncthreads();
    u64* rbuf = (u64*)ws;                             // reuse ws region
    if (hhalf == 1) {
        #pragma unroll
        for (int j = 0; j < 5; ++j) rbuf[px * 5 + j] = acc[j];
    }
    __syncthreads();
    if (hhalf == 0) {
        const int sp = (h0 + ph) * WB + (w0 + pw);
        float* ob = g_enc + (size_t)(b * CENC + co0) * HWB + sp;
        #pragma unroll
        for (int j = 0; j < 5; ++j) {
            float2 a  = unpack2(acc[j]);
            float2 r2 = unpack2(rbuf[px * 5 + j]);
            ob[(2 * j)     * HWB] = a.x + r2.x;
            ob[(2 * j + 1) * HWB] = a.y + r2.y;
        }
    }
}

// ---------------------------------------------------------------------------
// K3: fused softmax + reassembly.
// Weight source quirk: t2=2*pw+d/2; si=t2/40; wc=t2%40; sj=d&1;
//   logit_k = enc[b, k*4+si*2+sj, ph, wc].
// smem weights interleaved [pl][k*4+d] so (d0,d1)/(d2,d3) preload as LDS.64
// pairs into 50 b64 regs; inner loop = 25 pred-LDG + 25 pack + 50 FFMA2.
// grid (50 px-chunks, 4 c-groups of 64, 2 batch) x 256 threads.
// ---------------------------------------------------------------------------
__global__ __launch_bounds__(256) void k3_reassemble(
    const float* __restrict__ x, float* __restrict__ out)
{
    __shared__ __align__(16) float wsm[32 * 104];     // [pl][k*4+d], stride 104

    const int p0 = blockIdx.x * 32;
    const int c0 = blockIdx.y * 64;
    const int b  = blockIdx.z;
    const int tid = threadIdx.x;

    // ---- Phase A: softmax for 32 pixels x 4 subpixels (128 threads)
    if (tid < 128) {
        const int pl = tid & 31, d = tid >> 5;
        const int p  = p0 + pl;
        const int ph = p / WB, pw = p % WB;
        const int t2 = 2 * pw + (d >> 1);
        const int si = (t2 >= WB) ? 1 : 0;
        const int wc = t2 - WB * si;
        const int sj = d & 1;
        const float* ebase = g_enc + (size_t)(b * CENC + si * 2 + sj) * HWB + ph * WB + wc;

        float v[25];
        #pragma unroll
        for (int k = 0; k < 25; ++k) v[k] = ebase[(size_t)k * 4 * HWB];
        float m = v[0];
        #pragma unroll
        for (int k = 1; k < 25; ++k) m = fmaxf(m, v[k]);
        float s = 0.f;
        #pragma unroll
        for (int k = 0; k < 25; ++k) { v[k] = __expf(v[k] - m); s += v[k]; }
        float inv = 1.f / s;
        #pragma unroll
        for (int k = 0; k < 25; ++k) wsm[pl * 104 + k * 4 + d] = v[k] * inv;
    }
    __syncthreads();

    // ---- Phase B: reassembly
    const int pl = tid & 31, cq = tid >> 5;           // cq 0..7
    const int p  = p0 + pl;
    const int ph = p / WB, pw = p % WB;

    unsigned mask = 0;
    #pragma unroll
    for (int k = 0; k < 25; ++k) {
        int di = k / 5 - 2, dj = k % 5 - 2;
        if ((unsigned)(ph + di) < (unsigned)HB && (unsigned)(pw + dj) < (unsigned)WB)
            mask |= 1u << k;
    }

    u64 wrA[25], wrB[25];                             // (d0,d1) / (d2,d3)
    #pragma unroll
    for (int k = 0; k < 25; ++k) {
        wrA[k] = *(const u64*)&wsm[pl * 104 + k * 4];
        wrB[k] = *(const u64*)&wsm[pl * 104 + k * 4 + 2];
    }

    for (int it = 0; it < 8; ++it) {
        const int c = c0 + cq + (it << 3);
        const float* xb = x + (size_t)(b * CIN + c) * HWB + p;
        u64 accA = 0, accB = 0;
        #pragma unroll
        for (int k = 0; k < 25; ++k) {
            float xv = 0.f;
            if (mask & (1u << k))
                xv = __ldg(xb + (k / 5 - 2) * WB + (k % 5 - 2));
            u64 xx = pack2(xv, xv);
            ffma2(accA, xx, wrA[k]);
            ffma2(accB, xx, wrB[k]);
        }
        float2 a = unpack2(accA), bb = unpack2(accB);
        *reinterpret_cast<float4*>(out + (size_t)(b * CIN + c) * (HWB * 4) + 4 * p)
            = make_float4(a.x, a.y, bb.x, bb.y);
    }
}

// ---------------------------------------------------------------------------
extern "C" void kernel_launch(void* const* d_in, const int* in_sizes, int n_in,
                              void* d_out, int out_size)
{
    const float* x      = (const float*)d_in[0];   // (2,256,40,40)
    const float* w_comp = (const float*)d_in[1];   // (64,256,1,1)
    const float* w_enc  = (const float*)d_in[2];   // (100,64,3,3)
    float* out = (float*)d_out;                    // (2,256,80,80)

    k1_compress  <<<dim3(10, 8, 2),  160>>>(x, w_comp);
    k2_encoder   <<<dim3(25, 10, 2), 128>>>(w_enc);
    k3_reassemble<<<dim3(50, 4, 2),  256>>>(x, out);
}

// round 7
// speedup vs baseline: 1.5569x; 1.0579x over previous
#include <cuda_runtime.h>

#define HB 40
#define WB 40
#define HWB 1600          // 40*40
#define CIN 256
#define CMID 64
#define CENC 100
#define NBATCH 2

// Scratch (device globals; no allocation allowed)
__device__ float g_comp[NBATCH * CMID * HWB];   // (b,64,40,40)
__device__ float g_enc[NBATCH * CENC * HWB];    // (b,100,40,40)

typedef unsigned long long u64;

// ---- packed fp32x2 helpers (sm_103a FFMA2 via PTX) ----
__device__ __forceinline__ u64 pack2(float x, float y) {
    u64 r; asm("mov.b64 %0, {%1, %2};" : "=l"(r) : "f"(x), "f"(y)); return r;
}
__device__ __forceinline__ void ffma2(u64 &d, u64 a, u64 b) {
    asm("fma.rn.f32x2 %0, %1, %2, %0;" : "+l"(d) : "l"(a), "l"(b));
}
__device__ __forceinline__ float2 unpack2(u64 v) {
    float2 f; asm("mov.b64 {%0, %1}, %2;" : "=f"(f.x), "=f"(f.y) : "l"(v)); return f;
}

// ---------------------------------------------------------------------------
// K1: 1x1 conv, ci-split x4 inside the block (deterministic smem reduce).
// Block = 320 threads = 80 px * 4 ci-splits; thread: 64 ci, 8 co (4 FFMA2/ci).
// grid (20 px-chunks, 8 co-groups, 2 batch) = 320 blocks x 10 warps.
// ---------------------------------------------------------------------------
__global__ __launch_bounds__(320) void k1_compress(
    const float* __restrict__ x, const float* __restrict__ wcomp)
{
    __shared__ __align__(16) float ws[CIN * 8];   // [ci][co(8)]
    __shared__ __align__(16) u64 red[3 * 80 * 4]; // splits 1..3 partials

    const int tid   = threadIdx.x;
    const int px    = tid % 80;
    const int split = tid / 80;                   // 0..3
    const int p     = blockIdx.x * 80 + px;       // 20*80 = 1600 = HWB
    const int co0   = blockIdx.y * 8;
    const int b     = blockIdx.z;

    for (int i = tid; i < CIN * 8; i += 320) {
        int co = i >> 8, ci = i & 255;            // coalesced read in ci
        ws[ci * 8 + co] = wcomp[(co0 + co) * CIN + ci];
    }
    __syncthreads();

    const int ci0 = split * 64;
    const float* xb = x + (size_t)(b * CIN + ci0) * HWB + p;
    u64 acc0 = 0, acc1 = 0, acc2 = 0, acc3 = 0;   // (0.f,0.f)

    #pragma unroll 16
    for (int ci = 0; ci < 64; ++ci) {
        float xv = xb[(size_t)ci * HWB];
        u64 xx = pack2(xv, xv);
        const u64* wr = (const u64*)&ws[(ci0 + ci) * 8];  // broadcast LDS.64
        ffma2(acc0, xx, wr[0]);
        ffma2(acc1, xx, wr[1]);
        ffma2(acc2, xx, wr[2]);
        ffma2(acc3, xx, wr[3]);
    }

    if (split > 0) {
        u64* r = &red[((split - 1) * 80 + px) * 4];
        r[0] = acc0; r[1] = acc1; r[2] = acc2; r[3] = acc3;
    }
    __syncthreads();

    if (split == 0) {
        const u64 one = pack2(1.f, 1.f);
        #pragma unroll
        for (int s = 0; s < 3; ++s) {
            const u64* r = &red[(s * 80 + px) * 4];
            ffma2(acc0, one, r[0]);
            ffma2(acc1, one, r[1]);
            ffma2(acc2, one, r[2]);
            ffma2(acc3, one, r[3]);
        }
        float* ob = g_comp + (size_t)(b * CMID + co0) * HWB + p;
        float2 v;
        v = unpack2(acc0); ob[0 * HWB] = v.x; ob[1 * HWB] = v.y;
        v = unpack2(acc1); ob[2 * HWB] = v.x; ob[3 * HWB] = v.y;
        v = unpack2(acc2); ob[4 * HWB] = v.x; ob[5 * HWB] = v.y;
        v = unpack2(acc3); ob[6 * HWB] = v.x; ob[7 * HWB] = v.y;
    }
}

// ---------------------------------------------------------------------------
// K2: 3x3 conv 64->100, pad 1. Block: 8x8 px tile x 10 co.
// 128 threads = 64 px x 2 ci-halves; thread computes all 10 co over 32 ci
// (5 FFMA2 per tap), then smem reduce across halves.
// ---------------------------------------------------------------------------
__global__ __launch_bounds__(128) void k2_encoder(const float* __restrict__ wenc)
{
    __shared__ __align__(16) float xs[64 * 100];      // [ci][10x10 halo]
    __shared__ __align__(16) float ws[576 * 10];      // [ci*9+tap][co]

    const int tile = blockIdx.x;                      // 0..24
    const int co0  = blockIdx.y * 10;
    const int b    = blockIdx.z;
    const int h0 = (tile / 5) * 8, w0 = (tile % 5) * 8;
    const int tid = threadIdx.x;

    for (int i = tid; i < 64 * 100; i += 128) {
        int ci = i / 100, r = i - ci * 100;
        int hh = r / 10, ww = r - hh * 10;
        int gh = h0 - 1 + hh, gw = w0 - 1 + ww;
        float v = 0.f;
        if ((unsigned)gh < (unsigned)HB && (unsigned)gw < (unsigned)WB)
            v = g_comp[(b * CMID + ci) * HWB + gh * WB + gw];
        xs[i] = v;
    }
    for (int i = tid; i < 5760; i += 128) {
        int c = i / 576, idx = i - c * 576;           // coalesced read in idx
        ws[idx * 10 + c] = wenc[(co0 + c) * 576 + idx];
    }
    __syncthreads();

    const int px = tid & 63;
    const int hhalf = tid >> 6;                       // ci half
    const int ph = px >> 3, pw = px & 7;

    u64 acc[5] = {0, 0, 0, 0, 0};
    const int ci0 = hhalf * 32;

    #pragma unroll 2
    for (int ci = ci0; ci < ci0 + 32; ++ci) {
        const float* xrow = &xs[ci * 100 + ph * 10 + pw];
        const float* wb0  = &ws[ci * 90];
        #pragma unroll
        for (int tr = 0; tr < 3; ++tr)
        #pragma unroll
        for (int tc = 0; tc < 3; ++tc) {
            float xv = xrow[tr * 10 + tc];
            u64 xx = pack2(xv, xv);
            const u64* wp = (const u64*)(wb0 + (tr * 3 + tc) * 10);
            ffma2(acc[0], xx, wp[0]);
            ffma2(acc[1], xx, wp[1]);
            ffma2(acc[2], xx, wp[2]);
            ffma2(acc[3], xx, wp[3]);
            ffma2(acc[4], xx, wp[4]);
        }
    }

    __syncthreads();
    u64* rbuf = (u64*)ws;                             // reuse ws region
    if (hhalf == 1) {
        #pragma unroll
        for (int j = 0; j < 5; ++j) rbuf[px * 5 + j] = acc[j];
    }
    __syncthreads();
    if (hhalf == 0) {
        const int sp = (h0 + ph) * WB + (w0 + pw);
        float* ob = g_enc + (size_t)(b * CENC + co0) * HWB + sp;
        #pragma unroll
        for (int j = 0; j < 5; ++j) {
            float2 a  = unpack2(acc[j]);
            float2 r2 = unpack2(rbuf[px * 5 + j]);
            ob[(2 * j)     * HWB] = a.x + r2.x;
            ob[(2 * j + 1) * HWB] = a.y + r2.y;
        }
    }
}

// ---------------------------------------------------------------------------
// K3: fused softmax + reassembly.
// Weight source quirk: t2=2*pw+d/2; si=t2/40; wc=t2%40; sj=d&1;
//   logit_k = enc[b, k*4+si*2+sj, ph, wc].
// smem weights interleaved [pl][k*4+d]; inner loop = 25 pred-LDG + 25 pack
// + 50 FFMA2 per 100 MACs. grid (50, 4, 2) x 256 threads.
// ---------------------------------------------------------------------------
__global__ __launch_bounds__(256) void k3_reassemble(
    const float* __restrict__ x, float* __restrict__ out)
{
    __shared__ __align__(16) float wsm[32 * 104];     // [pl][k*4+d], stride 104

    const int p0 = blockIdx.x * 32;
    const int c0 = blockIdx.y * 64;
    const int b  = blockIdx.z;
    const int tid = threadIdx.x;

    // ---- Phase A: softmax for 32 pixels x 4 subpixels (128 threads)
    if (tid < 128) {
        const int pl = tid & 31, d = tid >> 5;
        const int p  = p0 + pl;
        const int ph = p / WB, pw = p % WB;
        const int t2 = 2 * pw + (d >> 1);
        const int si = (t2 >= WB) ? 1 : 0;
        const int wc = t2 - WB * si;
        const int sj = d & 1;
        const float* ebase = g_enc + (size_t)(b * CENC + si * 2 + sj) * HWB + ph * WB + wc;

        float v[25];
        #pragma unroll
        for (int k = 0; k < 25; ++k) v[k] = ebase[(size_t)k * 4 * HWB];
        float m = v[0];
        #pragma unroll
        for (int k = 1; k < 25; ++k) m = fmaxf(m, v[k]);
        float s = 0.f;
        #pragma unroll
        for (int k = 0; k < 25; ++k) { v[k] = __expf(v[k] - m); s += v[k]; }
        float inv = 1.f / s;
        #pragma unroll
        for (int k = 0; k < 25; ++k) wsm[pl * 104 + k * 4 + d] = v[k] * inv;
    }
    __syncthreads();

    // ---- Phase B: reassembly
    const int pl = tid & 31, cq = tid >> 5;           // cq 0..7
    const int p  = p0 + pl;
    const int ph = p / WB, pw = p % WB;

    unsigned mask = 0;
    #pragma unroll
    for (int k = 0; k < 25; ++k) {
        int di = k / 5 - 2, dj = k % 5 - 2;
        if ((unsigned)(ph + di) < (unsigned)HB && (unsigned)(pw + dj) < (unsigned)WB)
            mask |= 1u << k;
    }

    u64 wrA[25], wrB[25];                             // (d0,d1) / (d2,d3)
    #pragma unroll
    for (int k = 0; k < 25; ++k) {
        wrA[k] = *(const u64*)&wsm[pl * 104 + k * 4];
        wrB[k] = *(const u64*)&wsm[pl * 104 + k * 4 + 2];
    }

    for (int it = 0; it < 8; ++it) {
        const int c = c0 + cq + (it << 3);
        const float* xb = x + (size_t)(b * CIN + c) * HWB + p;
        u64 accA = 0, accB = 0;
        #pragma unroll
        for (int k = 0; k < 25; ++k) {
            float xv = 0.f;
            if (mask & (1u << k))
                xv = __ldg(xb + (k / 5 - 2) * WB + (k % 5 - 2));
            u64 xx = pack2(xv, xv);
            ffma2(accA, xx, wrA[k]);
            ffma2(accB, xx, wrB[k]);
        }
        float2 a = unpack2(accA), bb = unpack2(accB);
        *reinterpret_cast<float4*>(out + (size_t)(b * CIN + c) * (HWB * 4) + 4 * p)
            = make_float4(a.x, a.y, bb.x, bb.y);
    }
}

// ---------------------------------------------------------------------------
extern "C" void kernel_launch(void* const* d_in, const int* in_sizes, int n_in,
                              void* d_out, int out_size)
{
    const float* x      = (const float*)d_in[0];   // (2,256,40,40)
    const float* w_comp = (const float*)d_in[1];   // (64,256,1,1)
    const float* w_enc  = (const float*)d_in[2];   // (100,64,3,3)
    float* out = (float*)d_out;                    // (2,256,80,80)

    k1_compress  <<<dim3(20, 8, 2),  320>>>(x, w_comp);
    k2_encoder   <<<dim3(25, 10, 2), 128>>>(w_enc);
    k3_reassemble<<<dim3(50, 4, 2),  256>>>(x, out);
}

// round 12
// speedup vs baseline: 1.7996x; 1.1559x over previous
#include <cuda_runtime.h>

#define HB 40
#define WB 40
#define HWB 1600          // 40*40
#define CIN 256
#define CMID 64
#define CENC 100
#define NBATCH 2

// Scratch (device globals; no allocation allowed)
__device__ float g_comp[NBATCH * CMID * HWB];   // (b,64,40,40)
__device__ float g_enc[NBATCH * CENC * HWB];    // (b,100,40,40)

typedef unsigned long long u64;

// ---- packed fp32x2 helpers (sm_103a FFMA2 via PTX) ----
__device__ __forceinline__ u64 pack2(float x, float y) {
    u64 r; asm("mov.b64 %0, {%1, %2};" : "=l"(r) : "f"(x), "f"(y)); return r;
}
__device__ __forceinline__ void ffma2(u64 &d, u64 a, u64 b) {
    asm("fma.rn.f32x2 %0, %1, %2, %0;" : "+l"(d) : "l"(a), "l"(b));
}
__device__ __forceinline__ float2 unpack2(u64 v) {
    float2 f; asm("mov.b64 {%0, %1}, %2;" : "=f"(f.x), "=f"(f.y) : "l"(v)); return f;
}

// ---------------------------------------------------------------------------
// K1: 1x1 conv, ci-split x8 inside the block (deterministic smem reduce).
// Block = 640 threads = 80 px * 8 ci-splits; thread: 32 ci, 8 co (4 FFMA2/ci).
// grid (20 px-chunks, 8 co-groups, 2 batch) = 320 blocks x 20 warps.
// ---------------------------------------------------------------------------
__global__ __launch_bounds__(640) void k1_compress(
    const float* __restrict__ x, const float* __restrict__ wcomp)
{
    __shared__ __align__(16) float ws[CIN * 8];   // [ci][co(8)]
    __shared__ __align__(16) u64 red[7 * 80 * 4]; // splits 1..7 partials

    const int tid   = threadIdx.x;
    const int px    = tid % 80;
    const int split = tid / 80;                   // 0..7
    const int p     = blockIdx.x * 80 + px;       // 20*80 = 1600 = HWB
    const int co0   = blockIdx.y * 8;
    const int b     = blockIdx.z;

    for (int i = tid; i < CIN * 8; i += 640) {
        int co = i >> 8, ci = i & 255;            // coalesced read in ci
        ws[ci * 8 + co] = wcomp[(co0 + co) * CIN + ci];
    }
    __syncthreads();

    const int ci0 = split * 32;
    const float* xb = x + (size_t)(b * CIN + ci0) * HWB + p;
    u64 acc0 = 0, acc1 = 0, acc2 = 0, acc3 = 0;   // (0.f,0.f)

    #pragma unroll 16
    for (int ci = 0; ci < 32; ++ci) {
        float xv = xb[(size_t)ci * HWB];
        u64 xx = pack2(xv, xv);
        const u64* wr = (const u64*)&ws[(ci0 + ci) * 8];  // broadcast LDS.64
        ffma2(acc0, xx, wr[0]);
        ffma2(acc1, xx, wr[1]);
        ffma2(acc2, xx, wr[2]);
        ffma2(acc3, xx, wr[3]);
    }

    if (split > 0) {
        u64* r = &red[((split - 1) * 80 + px) * 4];
        r[0] = acc0; r[1] = acc1; r[2] = acc2; r[3] = acc3;
    }
    __syncthreads();

    if (split == 0) {
        const u64 one = pack2(1.f, 1.f);
        #pragma unroll
        for (int s = 0; s < 7; ++s) {
            const u64* r = &red[(s * 80 + px) * 4];
            ffma2(acc0, one, r[0]);
            ffma2(acc1, one, r[1]);
            ffma2(acc2, one, r[2]);
            ffma2(acc3, one, r[3]);
        }
        float* ob = g_comp + (size_t)(b * CMID + co0) * HWB + p;
        float2 v;
        v = unpack2(acc0); ob[0 * HWB] = v.x; ob[1 * HWB] = v.y;
        v = unpack2(acc1); ob[2 * HWB] = v.x; ob[3 * HWB] = v.y;
        v = unpack2(acc2); ob[4 * HWB] = v.x; ob[5 * HWB] = v.y;
        v = unpack2(acc3); ob[6 * HWB] = v.x; ob[7 * HWB] = v.y;
    }
}

// ---------------------------------------------------------------------------
// K2: 3x3 conv 64->100, pad 1. Block: 8x8 px tile x 10 co, 128 threads.
// Thread = 4 px (row, col0..col0+3) x 10 co (5 co-pair accs), 8 ci-splits
// of 8 ci each. Weights two-phase loaded (32 ci per phase) to fit smem.
// Per tap: 4 x-LDS + 4 pack + 5 w-LDS.64 + 20 FFMA2 -> 40 MACs.
// Reduction over 8 splits in smem (aliases xs after main loop).
// ---------------------------------------------------------------------------
__global__ __launch_bounds__(128) void k2_encoder(const float* __restrict__ wenc)
{
    __shared__ __align__(16) float xs[64 * 100];  // [ci][10x10 halo]  25.6KB
    __shared__ __align__(16) float ws[288 * 10];  // [ci_l*9+tap][co]  11.5KB

    const int tile = blockIdx.x;                  // 0..24
    const int co0  = blockIdx.y * 10;
    const int b    = blockIdx.z;
    const int h0 = (tile / 5) * 8, w0 = (tile % 5) * 8;
    const int tid = threadIdx.x;

    // fill full input halo tile (all 64 ci)
    for (int i = tid; i < 64 * 100; i += 128) {
        int ci = i / 100, r = i - ci * 100;
        int hh = r / 10, ww = r - hh * 10;
        int gh = h0 - 1 + hh, gw = w0 - 1 + ww;
        float v = 0.f;
        if ((unsigned)gh < (unsigned)HB && (unsigned)gw < (unsigned)WB)
            v = g_comp[(b * CMID + ci) * HWB + gh * WB + gw];
        xs[i] = v;
    }

    const int pxg   = tid & 15;                   // 16 groups of 4 px
    const int split = tid >> 4;                   // 0..7
    const int row   = pxg >> 1;                   // 0..7
    const int col0  = (pxg & 1) * 4;              // 0 or 4

    u64 acc[5][4];
    #pragma unroll
    for (int j = 0; j < 5; ++j)
        #pragma unroll
        for (int q = 0; q < 4; ++q) acc[j][q] = 0;

    #pragma unroll
    for (int phase = 0; phase < 2; ++phase) {
        if (phase) __syncthreads();               // phase0 reads done
        for (int i = tid; i < 2880; i += 128) {
            int c = i / 288, il = i - c * 288;    // coalesced in il
            ws[il * 10 + c] = wenc[(co0 + c) * 576 + phase * 288 + il];
        }
        __syncthreads();

        #pragma unroll
        for (int q4 = 0; q4 < 4; ++q4) {
            const int ci_l = split * 4 + q4;      // 0..31 within phase
            const int ci   = phase * 32 + ci_l;
            const float* xrow = &xs[ci * 100 + row * 10 + col0];
            const float* wb   = &ws[ci_l * 90];
            #pragma unroll
            for (int tr = 0; tr < 3; ++tr)
            #pragma unroll
            for (int tc = 0; tc < 3; ++tc) {
                const float* xr = xrow + tr * 10 + tc;
                u64 xx0 = pack2(xr[0], xr[0]);
                u64 xx1 = pack2(xr[1], xr[1]);
                u64 xx2 = pack2(xr[2], xr[2]);
                u64 xx3 = pack2(xr[3], xr[3]);
                const u64* wp = (const u64*)(wb + (tr * 3 + tc) * 10);
                #pragma unroll
                for (int j = 0; j < 5; ++j) {
                    u64 w = wp[j];
                    ffma2(acc[j][0], xx0, w);
                    ffma2(acc[j][1], xx1, w);
                    ffma2(acc[j][2], xx2, w);
                    ffma2(acc[j][3], xx3, w);
                }
            }
        }
    }

    __syncthreads();                              // xs reads complete
    u64* red = (u64*)xs;                          // alias: 7*16*20 u64 = 17.9KB
    if (split > 0) {
        u64* r = &red[((split - 1) * 16 + pxg) * 20];
        #pragma unroll
        for (int j = 0; j < 5; ++j)
            #pragma unroll
            for (int q = 0; q < 4; ++q) r[j * 4 + q] = acc[j][q];
    }
    __syncthreads();
    if (split == 0) {
        const u64 one = pack2(1.f, 1.f);
        #pragma unroll
        for (int s = 0; s < 7; ++s) {
            const u64* r = &red[(s * 16 + pxg) * 20];
            #pragma unroll
            for (int j = 0; j < 5; ++j)
                #pragma unroll
                for (int q = 0; q < 4; ++q) ffma2(acc[j][q], one, r[j * 4 + q]);
        }
        #pragma unroll
        for (int q = 0; q < 4; ++q) {
            const int sp = (h0 + row) * WB + (w0 + col0 + q);
            float* ob = g_enc + (size_t)(b * CENC + co0) * HWB + sp;
            #pragma unroll
            for (int j = 0; j < 5; ++j) {
                float2 v = unpack2(acc[j][q]);
                ob[(2 * j)     * HWB] = v.x;
                ob[(2 * j + 1) * HWB] = v.y;
            }
        }
    }
}

// ---------------------------------------------------------------------------
// K3: fused softmax + reassembly (unchanged; verified).
// t2=2*pw+d/2; si=t2/40; wc=t2%40; sj=d&1; logit_k = enc[b,k*4+si*2+sj,ph,wc].
// ---------------------------------------------------------------------------
__global__ __launch_bounds__(256) void k3_reassemble(
    const float* __restrict__ x, float* __restrict__ out)
{
    __shared__ __align__(16) float wsm[32 * 104];     // [pl][k*4+d], stride 104

    const int p0 = blockIdx.x * 32;
    const int c0 = blockIdx.y * 64;
    const int b  = blockIdx.z;
    const int tid = threadIdx.x;

    if (tid < 128) {
        const int pl = tid & 31, d = tid >> 5;
        const int p  = p0 + pl;
        const int ph = p / WB, pw = p % WB;
        const int t2 = 2 * pw + (d >> 1);
        const int si = (t2 >= WB) ? 1 : 0;
        const int wc = t2 - WB * si;
        const int sj = d & 1;
        const float* ebase = g_enc + (size_t)(b * CENC + si * 2 + sj) * HWB + ph * WB + wc;

        float v[25];
        #pragma unroll
        for (int k = 0; k < 25; ++k) v[k] = ebase[(size_t)k * 4 * HWB];
        float m = v[0];
        #pragma unroll
        for (int k = 1; k < 25; ++k) m = fmaxf(m, v[k]);
        float s = 0.f;
        #pragma unroll
        for (int k = 0; k < 25; ++k) { v[k] = __expf(v[k] - m); s += v[k]; }
        float inv = 1.f / s;
        #pragma unroll
        for (int k = 0; k < 25; ++k) wsm[pl * 104 + k * 4 + d] = v[k] * inv;
    }
    __syncthreads();

    const int pl = tid & 31, cq = tid >> 5;           // cq 0..7
    const int p  = p0 + pl;
    const int ph = p / WB, pw = p % WB;

    unsigned mask = 0;
    #pragma unroll
    for (int k = 0; k < 25; ++k) {
        int di = k / 5 - 2, dj = k % 5 - 2;
        if ((unsigned)(ph + di) < (unsigned)HB && (unsigned)(pw + dj) < (unsigned)WB)
            mask |= 1u << k;
    }

    u64 wrA[25], wrB[25];                             // (d0,d1) / (d2,d3)
    #pragma unroll
    for (int k = 0; k < 25; ++k) {
        wrA[k] = *(const u64*)&wsm[pl * 104 + k * 4];
        wrB[k] = *(const u64*)&wsm[pl * 104 + k * 4 + 2];
    }

    for (int it = 0; it < 8; ++it) {
        const int c = c0 + cq + (it << 3);
        const float* xb = x + (size_t)(b * CIN + c) * HWB + p;
        u64 accA = 0, accB = 0;
        #pragma unroll
        for (int k = 0; k < 25; ++k) {
            float xv = 0.f;
            if (mask & (1u << k))
                xv = __ldg(xb + (k / 5 - 2) * WB + (k % 5 - 2));
            u64 xx = pack2(xv, xv);
            ffma2(accA, xx, wrA[k]);
            ffma2(accB, xx, wrB[k]);
        }
        float2 a = unpack2(accA), bb = unpack2(accB);
        *reinterpret_cast<float4*>(out + (size_t)(b * CIN + c) * (HWB * 4) + 4 * p)
            = make_float4(a.x, a.y, bb.x, bb.y);
    }
}

// ---------------------------------------------------------------------------
extern "C" void kernel_launch(void* const* d_in, const int* in_sizes, int n_in,
                              void* d_out, int out_size)
{
    const float* x      = (const float*)d_in[0];   // (2,256,40,40)
    const float* w_comp = (const float*)d_in[1];   // (64,256,1,1)
    const float* w_enc  = (const float*)d_in[2];   // (100,64,3,3)
    float* out = (float*)d_out;                    // (2,256,80,80)

    k1_compress  <<<dim3(20, 8, 2),  640>>>(x, w_comp);
    k2_encoder   <<<dim3(25, 10, 2), 128>>>(w_enc);
    k3_reassemble<<<dim3(50, 4, 2),  256>>>(x, out);
}

// round 14
// speedup vs baseline: 1.8071x; 1.0042x over previous
#include <cuda_runtime.h>

#define HB 40
#define WB 40
#define HWB 1600          // 40*40
#define CIN 256
#define CMID 64
#define CENC 100
#define NBATCH 2

// Scratch (device globals; no allocation allowed)
__device__ float g_comp[NBATCH * CMID * HWB];   // (b,64,40,40)
__device__ float g_enc[NBATCH * CENC * HWB];    // (b,100,40,40)

typedef unsigned long long u64;

// ---- packed fp32x2 helpers (sm_103a FFMA2 via PTX) ----
__device__ __forceinline__ u64 pack2(float x, float y) {
    u64 r; asm("mov.b64 %0, {%1, %2};" : "=l"(r) : "f"(x), "f"(y)); return r;
}
__device__ __forceinline__ void ffma2(u64 &d, u64 a, u64 b) {
    asm("fma.rn.f32x2 %0, %1, %2, %0;" : "+l"(d) : "l"(a), "l"(b));
}
__device__ __forceinline__ float2 unpack2(u64 v) {
    float2 f; asm("mov.b64 {%0, %1}, %2;" : "=f"(f.x), "=f"(f.y) : "l"(v)); return f;
}

// ---------------------------------------------------------------------------
// K1: 1x1 conv, ci-split x8 inside the block (deterministic smem reduce).
// Block = 640 threads = 80 px * 8 ci-splits; thread: 32 ci, 8 co (4 FFMA2/ci).
// ---------------------------------------------------------------------------
__global__ __launch_bounds__(640) void k1_compress(
    const float* __restrict__ x, const float* __restrict__ wcomp)
{
    __shared__ __align__(16) float ws[CIN * 8];   // [ci][co(8)]
    __shared__ __align__(16) u64 red[7 * 80 * 4]; // splits 1..7 partials

    const int tid   = threadIdx.x;
    const int px    = tid % 80;
    const int split = tid / 80;                   // 0..7
    const int p     = blockIdx.x * 80 + px;       // 20*80 = 1600 = HWB
    const int co0   = blockIdx.y * 8;
    const int b     = blockIdx.z;

    for (int i = tid; i < CIN * 8; i += 640) {
        int co = i >> 8, ci = i & 255;            // coalesced read in ci
        ws[ci * 8 + co] = wcomp[(co0 + co) * CIN + ci];
    }
    __syncthreads();

    const int ci0 = split * 32;
    const float* xb = x + (size_t)(b * CIN + ci0) * HWB + p;
    u64 acc0 = 0, acc1 = 0, acc2 = 0, acc3 = 0;   // (0.f,0.f)

    #pragma unroll 16
    for (int ci = 0; ci < 32; ++ci) {
        float xv = xb[(size_t)ci * HWB];
        u64 xx = pack2(xv, xv);
        const u64* wr = (const u64*)&ws[(ci0 + ci) * 8];  // broadcast LDS.64
        ffma2(acc0, xx, wr[0]);
        ffma2(acc1, xx, wr[1]);
        ffma2(acc2, xx, wr[2]);
        ffma2(acc3, xx, wr[3]);
    }

    if (split > 0) {
        u64* r = &red[((split - 1) * 80 + px) * 4];
        r[0] = acc0; r[1] = acc1; r[2] = acc2; r[3] = acc3;
    }
    __syncthreads();

    if (split == 0) {
        const u64 one = pack2(1.f, 1.f);
        #pragma unroll
        for (int s = 0; s < 7; ++s) {
            const u64* r = &red[(s * 80 + px) * 4];
            ffma2(acc0, one, r[0]);
            ffma2(acc1, one, r[1]);
            ffma2(acc2, one, r[2]);
            ffma2(acc3, one, r[3]);
        }
        float* ob = g_comp + (size_t)(b * CMID + co0) * HWB + p;
        float2 v;
        v = unpack2(acc0); ob[0 * HWB] = v.x; ob[1 * HWB] = v.y;
        v = unpack2(acc1); ob[2 * HWB] = v.x; ob[3 * HWB] = v.y;
        v = unpack2(acc2); ob[4 * HWB] = v.x; ob[5 * HWB] = v.y;
        v = unpack2(acc3); ob[6 * HWB] = v.x; ob[7 * HWB] = v.y;
    }
}

// ---------------------------------------------------------------------------
// K2: 3x3 conv 64->100, pad 1. Block: 8x8 px tile x 10 co, 128 threads.
// Two ci-phases (32 ci each) to shrink smem -> multi-block residency.
// x tile stored DUPLICATED as u64 pairs (x,x), halo rows padded to stride 13
// u64 elems (<=2-way LDS bank conflict), so no pack MOVs in the main loop:
// per tap = 4 x-LDS.64 + 5 w-LDS.64 + 20 FFMA2 for 40 MACs.
// Thread = 4 px x 10 co; 8 splits x 4 ci per phase; smem reduce over splits.
// ---------------------------------------------------------------------------
__global__ __launch_bounds__(128) void k2_encoder(const float* __restrict__ wenc)
{
    // xs2: 32 ci * 130 u64 = 4160 u64 (33.3KB) | ws: 288*10 floats (11.5KB)
    __shared__ __align__(16) float smem_all[4160 * 2 + 2880];   // 44.8KB
    u64*   xs2 = (u64*)smem_all;
    float* ws  = smem_all + 4160 * 2;

    const int tile = blockIdx.x;                  // 0..24
    const int co0  = blockIdx.y * 10;
    const int b    = blockIdx.z;
    const int h0 = (tile / 5) * 8, w0 = (tile % 5) * 8;
    const int tid = threadIdx.x;

    const int pxg   = tid & 15;                   // 16 groups of 4 px
    const int split = tid >> 4;                   // 0..7
    const int row   = pxg >> 1;                   // 0..7
    const int col0  = (pxg & 1) * 4;              // 0 or 4

    u64 acc[5][4];
    #pragma unroll
    for (int j = 0; j < 5; ++j)
        #pragma unroll
        for (int q = 0; q < 4; ++q) acc[j][q] = 0;

    #pragma unroll
    for (int phase = 0; phase < 2; ++phase) {
        if (phase) __syncthreads();               // phase-0 reads complete
        // x halo tile for this ci-half, duplicated (x,x), row stride 13
        for (int i = tid; i < 3200; i += 128) {
            int ci_l = i / 100, r = i - ci_l * 100;
            int hh = r / 10, ww = r - hh * 10;
            int gh = h0 - 1 + hh, gw = w0 - 1 + ww;
            float v = 0.f;
            if ((unsigned)gh < (unsigned)HB && (unsigned)gw < (unsigned)WB)
                v = g_comp[(b * CMID + phase * 32 + ci_l) * HWB + gh * WB + gw];
            xs2[ci_l * 130 + hh * 13 + ww] = pack2(v, v);
        }
        // weight slice for this ci-half, layout [ci_l*9+tap][co]
        for (int i = tid; i < 2880; i += 128) {
            int c = i / 288, il = i - c * 288;    // coalesced in il
            ws[il * 10 + c] = wenc[(co0 + c) * 576 + phase * 288 + il];
        }
        __syncthreads();

        #pragma unroll
        for (int q4 = 0; q4 < 4; ++q4) {
            const int ci_l = split * 4 + q4;      // 0..31 within phase
            const u64*  xrow = xs2 + ci_l * 130 + row * 13 + col0;
            const float* wb  = &ws[ci_l * 90];
            #pragma unroll
            for (int tr = 0; tr < 3; ++tr)
            #pragma unroll
            for (int tc = 0; tc < 3; ++tc) {
                const u64* xr = xrow + tr * 13 + tc;
                u64 xx0 = xr[0], xx1 = xr[1], xx2 = xr[2], xx3 = xr[3];
                const u64* wp = (const u64*)(wb + (tr * 3 + tc) * 10);
                #pragma unroll
                for (int j = 0; j < 5; ++j) {
                    u64 w = wp[j];
                    ffma2(acc[j][0], xx0, w);
                    ffma2(acc[j][1], xx1, w);
                    ffma2(acc[j][2], xx2, w);
                    ffma2(acc[j][3], xx3, w);
                }
            }
        }
    }

    __syncthreads();                              // all smem reads complete
    u64* red = (u64*)smem_all;                    // 7*16*20 u64 = 17.9KB
    if (split > 0) {
        u64* r = &red[((split - 1) * 16 + pxg) * 20];
        #pragma unroll
        for (int j = 0; j < 5; ++j)
            #pragma unroll
            for (int q = 0; q < 4; ++q) r[j * 4 + q] = acc[j][q];
    }
    __syncthreads();
    if (split == 0) {
        const u64 one = pack2(1.f, 1.f);
        #pragma unroll
        for (int s = 0; s < 7; ++s) {
            const u64* r = &red[(s * 16 + pxg) * 20];
            #pragma unroll
            for (int j = 0; j < 5; ++j)
                #pragma unroll
                for (int q = 0; q < 4; ++q) ffma2(acc[j][q], one, r[j * 4 + q]);
        }
        #pragma unroll
        for (int q = 0; q < 4; ++q) {
            const int sp = (h0 + row) * WB + (w0 + col0 + q);
            float* ob = g_enc + (size_t)(b * CENC + co0) * HWB + sp;
            #pragma unroll
            for (int j = 0; j < 5; ++j) {
                float2 v = unpack2(acc[j][q]);
                ob[(2 * j)     * HWB] = v.x;
                ob[(2 * j + 1) * HWB] = v.y;
            }
        }
    }
}

// ---------------------------------------------------------------------------
// K3: fused softmax + reassembly (unchanged; verified).
// t2=2*pw+d/2; si=t2/40; wc=t2%40; sj=d&1; logit_k = enc[b,k*4+si*2+sj,ph,wc].
// ---------------------------------------------------------------------------
__global__ __launch_bounds__(256) void k3_reassemble(
    const float* __restrict__ x, float* __restrict__ out)
{
    __shared__ __align__(16) float wsm[32 * 104];     // [pl][k*4+d], stride 104

    const int p0 = blockIdx.x * 32;
    const int c0 = blockIdx.y * 64;
    const int b  = blockIdx.z;
    const int tid = threadIdx.x;

    if (tid < 128) {
        const int pl = tid & 31, d = tid >> 5;
        const int p  = p0 + pl;
        const int ph = p / WB, pw = p % WB;
        const int t2 = 2 * pw + (d >> 1);
        const int si = (t2 >= WB) ? 1 : 0;
        const int wc = t2 - WB * si;
        const int sj = d & 1;
        const float* ebase = g_enc + (size_t)(b * CENC + si * 2 + sj) * HWB + ph * WB + wc;

        float v[25];
        #pragma unroll
        for (int k = 0; k < 25; ++k) v[k] = ebase[(size_t)k * 4 * HWB];
        float m = v[0];
        #pragma unroll
        for (int k = 1; k < 25; ++k) m = fmaxf(m, v[k]);
        float s = 0.f;
        #pragma unroll
        for (int k = 0; k < 25; ++k) { v[k] = __expf(v[k] - m); s += v[k]; }
        float inv = 1.f / s;
        #pragma unroll
        for (int k = 0; k < 25; ++k) wsm[pl * 104 + k * 4 + d] = v[k] * inv;
    }
    __syncthreads();

    const int pl = tid & 31, cq = tid >> 5;           // cq 0..7
    const int p  = p0 + pl;
    const int ph = p / WB, pw = p % WB;

    unsigned mask = 0;
    #pragma unroll
    for (int k = 0; k < 25; ++k) {
        int di = k / 5 - 2, dj = k % 5 - 2;
        if ((unsigned)(ph + di) < (unsigned)HB && (unsigned)(pw + dj) < (unsigned)WB)
            mask |= 1u << k;
    }

    u64 wrA[25], wrB[25];                             // (d0,d1) / (d2,d3)
    #pragma unroll
    for (int k = 0; k < 25; ++k) {
        wrA[k] = *(const u64*)&wsm[pl * 104 + k * 4];
        wrB[k] = *(const u64*)&wsm[pl * 104 + k * 4 + 2];
    }

    for (int it = 0; it < 8; ++it) {
        const int c = c0 + cq + (it << 3);
        const float* xb = x + (size_t)(b * CIN + c) * HWB + p;
        u64 accA = 0, accB = 0;
        #pragma unroll
        for (int k = 0; k < 25; ++k) {
            float xv = 0.f;
            if (mask & (1u << k))
                xv = __ldg(xb + (k / 5 - 2) * WB + (k % 5 - 2));
            u64 xx = pack2(xv, xv);
            ffma2(accA, xx, wrA[k]);
            ffma2(accB, xx, wrB[k]);
        }
        float2 a = unpack2(accA), bb = unpack2(accB);
        *reinterpret_cast<float4*>(out + (size_t)(b * CIN + c) * (HWB * 4) + 4 * p)
            = make_float4(a.x, a.y, bb.x, bb.y);
    }
}

// ---------------------------------------------------------------------------
extern "C" void kernel_launch(void* const* d_in, const int* in_sizes, int n_in,
                              void* d_out, int out_size)
{
    const float* x      = (const float*)d_in[0];   // (2,256,40,40)
    const float* w_comp = (const float*)d_in[1];   // (64,256,1,1)
    const float* w_enc  = (const float*)d_in[2];   // (100,64,3,3)
    float* out = (float*)d_out;                    // (2,256,80,80)

    k1_compress  <<<dim3(20, 8, 2),  640>>>(x, w_comp);
    k2_encoder   <<<dim3(25, 10, 2), 128>>>(w_enc);
    k3_reassemble<<<dim3(50, 4, 2),  256>>>(x, out);
}